// round 5
// baseline (speedup 1.0000x reference)
#include <cuda_runtime.h>
#include <cuda_bf16.h>
#include <cuda_fp8.h>
#include <cstdint>

// Energy-distance loss, FP8 (e4m3) QMMA version.
//   loss = mean_b[ mean||x-y|| - 0.5 mean||x-x'|| - 0.5 mean||y-y'|| ]
// Grams via mma.sync.m16n8k32.e4m3 (fp32 accum, 2x legacy HMMA rate);
// norms fp32-exact from ORIGINAL fp32 data; diagonal excluded analytically.
// Element quantization noise cancels between cross and self terms
// (measured: bf16 vs fp32 Gram changed rel_err by only ~1.5e-6).

#define NPTS  512
#define DIMS  128
#define NB    128
#define NROWS 65536
#define N_CROSS_CTAS 2048
#define N_SELF_CTAS  1280
#define N_JOBS (N_CROSS_CTAS + 2 * N_SELF_CTAS)   // 4608
#define JOBS_PER_CTA 16
#define N_CTAS ((N_JOBS + JOBS_PER_CTA - 1) / JOBS_PER_CTA)   // 288

__device__ uint8_t g_fx[NROWS * DIMS];   // 8 MB e4m3
__device__ uint8_t g_fy[NROWS * DIMS];   // 8 MB e4m3
__device__ float g_norm_x[NROWS];
__device__ float g_norm_y[NROWS];
__device__ float g_partials[N_JOBS];

// smem layout (bytes, from 1024-aligned base)
#define OFF_A    0        // 16 KB fp8 tile, 128B rows, xor-swizzled
#define OFF_B    16384    // 16 KB
#define OFF_NX   32768    // 512 B
#define OFF_NY   33280    // 512 B
#define OFF_RED  33792    // 32 B
#define SMEM_REQ (1024 + 33824)

__device__ __forceinline__ uint32_t smem_u32(const void* p) {
    uint32_t a;
    asm("{ .reg .u64 t; cvta.to.shared.u64 t, %1; cvt.u32.u64 %0, t; }"
        : "=r"(a) : "l"(p));
    return a;
}

// ---------------------------------------------------------------------------
// Kernel 0: fp32 -> e4m3 convert + exact fp32 squared norms.
// One warp handles 4 rows; each lane: 4 floats -> 4 fp8 bytes (coalesced).
// ---------------------------------------------------------------------------
__global__ void prep_kernel(const float* __restrict__ X,
                            const float* __restrict__ Y) {
    int warp = (blockIdx.x * blockDim.x + threadIdx.x) >> 5;
    int lane = threadIdx.x & 31;
    int row4 = warp * 4;
    const float* src; uint8_t* dst; float* ndst; int r0;
    if (row4 < NROWS) { src = X; dst = g_fx; ndst = g_norm_x; r0 = row4; }
    else              { src = Y; dst = g_fy; ndst = g_norm_y; r0 = row4 - NROWS; }

    float4 v[4];
    float s[4];
#pragma unroll
    for (int k = 0; k < 4; k++) {
        v[k] = ((const float4*)(src + (size_t)(r0 + k) * DIMS))[lane];
        s[k] = v[k].x * v[k].x + v[k].y * v[k].y + v[k].z * v[k].z + v[k].w * v[k].w;
    }
#pragma unroll
    for (int k = 0; k < 4; k++) {
        float2 lo = make_float2(v[k].x, v[k].y);
        float2 hi = make_float2(v[k].z, v[k].w);
        unsigned p0 = __nv_cvt_float2_to_fp8x2(lo, __NV_SATFINITE, __NV_E4M3);
        unsigned p1 = __nv_cvt_float2_to_fp8x2(hi, __NV_SATFINITE, __NV_E4M3);
        unsigned packed = (p0 & 0xffffu) | (p1 << 16);
        *(unsigned*)(dst + (size_t)(r0 + k) * DIMS + lane * 4) = packed;
#pragma unroll
        for (int o = 16; o; o >>= 1) s[k] += __shfl_xor_sync(0xffffffffu, s[k], o);
        if (lane == 0) ndst[r0 + k] = s[k];
    }
}

// ---------------------------------------------------------------------------
// Kernel 1: 128x128 distance tiles via e4m3 mma.sync.m16n8k32.
// 8 warps in 4(m) x 2(n); warp tile 32x64 = 2 x 8 (m16n8) x 4 k32 chunks.
// Chunked persistent schedule with A-tile reuse; cp.async staging.
// ---------------------------------------------------------------------------
__global__ __launch_bounds__(256, 2)
void dist_kernel() {
    extern __shared__ char dyn_smem[];
    char* sm = (char*)((((uintptr_t)dyn_smem) + 1023) & ~(uintptr_t)1023);
    uint32_t sbase = smem_u32(sm);

    int tid  = threadIdx.x;
    int lane = tid & 31;
    int warp = tid >> 5;
    int wm   = warp >> 1;      // 0..3: 32-row band
    int wn   = warp & 1;       // 0..1: 64-col band

    // ldmatrix lane-address components (uint4 granularity, 128B rows)
    int a_r = (lane & 7) + ((lane >> 3) & 1) * 8;
    int a_u = lane >> 4;
    int b_r = (lane & 7) + ((lane >> 4) << 3);
    int b_u = (lane >> 3) & 1;

    int j0 = blockIdx.x * JOBS_PER_CTA;
    int j1 = j0 + JOBS_PER_CTA;
    if (j1 > N_JOBS) j1 = N_JOBS;

    const uint8_t* prevAbase = (const uint8_t*)0;

    for (int job = j0; job < j1; job++) {
        // ---- job decode ----
        const uint8_t *Ap, *Bp;
        const float *nAp, *nBp;
        int b, tr, tc;
        bool selfm;
        if (job < N_CROSS_CTAS) {
            b = job >> 4;
            int t = job & 15;
            tr = t >> 2; tc = t & 3;          // runs of 4 share (b,tr)
            Ap = g_fx; Bp = g_fy; nAp = g_norm_x; nBp = g_norm_y;
            selfm = false;
        } else {
            int r = job - N_CROSS_CTAS;
            int isY = (r >= N_SELF_CTAS);
            if (isY) r -= N_SELF_CTAS;
            b = r / 10;
            int t = r - b * 10;
            int trr = 0, tt = t;
            while (tt >= 4 - trr) { tt -= 4 - trr; trr++; }
            tr = trr; tc = trr + tt;
            Ap = isY ? g_fy : g_fx;
            Bp = Ap;
            nAp = isY ? g_norm_y : g_norm_x;
            nBp = nAp;
            selfm = true;
        }
        bool diag = selfm && (tr == tc);
        const uint8_t* Abase = Ap + ((size_t)b * NPTS + tr * 128) * DIMS;
        const uint8_t* Bbase = Bp + ((size_t)b * NPTS + tc * 128) * DIMS;
        bool reuseA = (Abase == prevAbase);
        prevAbase = Abase;

        __syncthreads();   // prior job fully done with smem

        // ---- stage via cp.async: 1024 uint4 per matrix ----
        // row r: 128 bytes = 8 uint4; swizzle: u ^ (r & 7)
#pragma unroll
        for (int q = 0; q < 4; q++) {
            int idx = tid + q * 256;           // 0..1023
            int r = idx >> 3, u = idx & 7;
            int soff = r * 128 + ((u ^ (r & 7)) << 4);
            const void* srcB = (const void*)(Bbase + (size_t)r * DIMS + u * 16);
            asm volatile("cp.async.cg.shared.global [%0], [%1], 16;"
                         :: "r"(sbase + OFF_B + soff), "l"(srcB));
            if (!reuseA) {
                const void* srcA = (const void*)(Abase + (size_t)r * DIMS + u * 16);
                asm volatile("cp.async.cg.shared.global [%0], [%1], 16;"
                             :: "r"(sbase + OFF_A + soff), "l"(srcA));
            }
        }
        if (tid < 128) {
            if (!reuseA)
                *(float*)(sm + OFF_NX + tid * 4) = nAp[b * NPTS + tr * 128 + tid];
        } else {
            *(float*)(sm + OFF_NY + (tid - 128) * 4) = nBp[b * NPTS + tc * 128 + tid - 128];
        }
        asm volatile("cp.async.commit_group;");
        asm volatile("cp.async.wait_group 0;" ::: "memory");
        __syncthreads();

        // ---- mainloop: 4 k32 chunks ----
        float acc[2][8][4];
#pragma unroll
        for (int mt = 0; mt < 2; mt++)
#pragma unroll
            for (int nt = 0; nt < 8; nt++)
#pragma unroll
                for (int c = 0; c < 4; c++) acc[mt][nt][c] = 0.f;

        uint32_t sA = sbase + OFF_A;
        uint32_t sB = sbase + OFF_B;

#pragma unroll
        for (int kk = 0; kk < 4; kk++) {       // k32 chunk = 32 bytes = 2 uint4
            unsigned af[2][4];
#pragma unroll
            for (int mt = 0; mt < 2; mt++) {
                int r = wm * 32 + mt * 16 + a_r;
                int u = kk * 2 + a_u;
                unsigned addr = sA + (unsigned)(r * 128 + ((u ^ (r & 7)) << 4));
                asm volatile(
                    "ldmatrix.sync.aligned.m8n8.x4.shared.b16 {%0,%1,%2,%3}, [%4];"
                    : "=r"(af[mt][0]), "=r"(af[mt][1]), "=r"(af[mt][2]), "=r"(af[mt][3])
                    : "r"(addr));
            }
#pragma unroll
            for (int p = 0; p < 4; p++) {
                int r = wn * 64 + p * 16 + b_r;
                int u = kk * 2 + b_u;
                unsigned addr = sB + (unsigned)(r * 128 + ((u ^ (r & 7)) << 4));
                unsigned bf[4];
                asm volatile(
                    "ldmatrix.sync.aligned.m8n8.x4.shared.b16 {%0,%1,%2,%3}, [%4];"
                    : "=r"(bf[0]), "=r"(bf[1]), "=r"(bf[2]), "=r"(bf[3])
                    : "r"(addr));
                // n8 tile 2p: k-bytes {0-15,16-31} = {bf0, bf1}; tile 2p+1: {bf2, bf3}
#pragma unroll
                for (int mt = 0; mt < 2; mt++) {
                    asm volatile(
                        "mma.sync.aligned.m16n8k32.row.col.f32.e4m3.e4m3.f32 "
                        "{%0,%1,%2,%3}, {%4,%5,%6,%7}, {%8,%9}, {%0,%1,%2,%3};"
                        : "+f"(acc[mt][2*p][0]), "+f"(acc[mt][2*p][1]),
                          "+f"(acc[mt][2*p][2]), "+f"(acc[mt][2*p][3])
                        : "r"(af[mt][0]), "r"(af[mt][1]), "r"(af[mt][2]), "r"(af[mt][3]),
                          "r"(bf[0]), "r"(bf[1]));
                    asm volatile(
                        "mma.sync.aligned.m16n8k32.row.col.f32.e4m3.e4m3.f32 "
                        "{%0,%1,%2,%3}, {%4,%5,%6,%7}, {%8,%9}, {%0,%1,%2,%3};"
                        : "+f"(acc[mt][2*p+1][0]), "+f"(acc[mt][2*p+1][1]),
                          "+f"(acc[mt][2*p+1][2]), "+f"(acc[mt][2*p+1][3])
                        : "r"(af[mt][0]), "r"(af[mt][1]), "r"(af[mt][2]), "r"(af[mt][3]),
                          "r"(bf[2]), "r"(bf[3]));
                }
            }
        }

        // ---- epilogue ----
        int g  = lane >> 2;
        int ct = lane & 3;

        int   irow[2][2];
        float nx[2][2];
#pragma unroll
        for (int mt = 0; mt < 2; mt++) {
            int r0 = wm * 32 + mt * 16 + g;
            irow[mt][0] = tr * 128 + r0;
            irow[mt][1] = irow[mt][0] + 8;
            nx[mt][0] = *(const float*)(sm + OFF_NX + r0 * 4);
            nx[mt][1] = *(const float*)(sm + OFF_NX + (r0 + 8) * 4);
        }
        int   jcol[8][2];
        float ny[8][2];
#pragma unroll
        for (int nt = 0; nt < 8; nt++) {
            int c0 = wn * 64 + nt * 8 + 2 * ct;
            jcol[nt][0] = tc * 128 + c0;
            jcol[nt][1] = jcol[nt][0] + 1;
            ny[nt][0] = *(const float*)(sm + OFF_NY + c0 * 4);
            ny[nt][1] = *(const float*)(sm + OFF_NY + (c0 + 1) * 4);
        }

        float tsum = 0.f;
        if (diag) {
#pragma unroll
            for (int mt = 0; mt < 2; mt++)
#pragma unroll
                for (int nt = 0; nt < 8; nt++)
#pragma unroll
                    for (int c = 0; c < 4; c++) {
                        int ri = c >> 1, cj = c & 1;
                        float d2 = nx[mt][ri] + ny[nt][cj] - 2.f * acc[mt][nt][c];
                        float dd;
                        asm("sqrt.approx.f32 %0, %1;" : "=f"(dd) : "f"(d2));
                        if (!(d2 > 0.f) || jcol[nt][cj] <= irow[mt][ri]) dd = 0.f;
                        tsum += dd;
                    }
        } else {
#pragma unroll
            for (int mt = 0; mt < 2; mt++)
#pragma unroll
                for (int nt = 0; nt < 8; nt++)
#pragma unroll
                    for (int c = 0; c < 4; c++) {
                        int ri = c >> 1, cj = c & 1;
                        float d2 = nx[mt][ri] + ny[nt][cj] - 2.f * acc[mt][nt][c];
                        float dd;
                        asm("sqrt.approx.f32 %0, %1;" : "=f"(dd) : "f"(d2));
                        if (!(d2 > 0.f)) dd = 0.f;
                        tsum += dd;
                    }
        }

#pragma unroll
        for (int o = 16; o; o >>= 1) tsum += __shfl_xor_sync(0xffffffffu, tsum, o);
        if (lane == 0) *(float*)(sm + OFF_RED + warp * 4) = tsum;
        __syncthreads();
        if (tid == 0) {
            float s = 0.f;
#pragma unroll
            for (int w = 0; w < 8; w++) s += *(float*)(sm + OFF_RED + w * 4);
            g_partials[job] = s;
        }
    }
}

// ---------------------------------------------------------------------------
// Kernel 2: deterministic double-precision finalize.
// ---------------------------------------------------------------------------
__global__ void finalize_kernel(float* __restrict__ out) {
    __shared__ double sd[256];
    int tid = threadIdx.x;
    double s = 0.0;
    for (int i = tid; i < N_JOBS; i += 256) {
        double v = (double)g_partials[i];
        s += (i < N_CROSS_CTAS) ? v : -v;
    }
    sd[tid] = s;
    __syncthreads();
    for (int o = 128; o; o >>= 1) {
        if (tid < o) sd[tid] += sd[tid + o];
        __syncthreads();
    }
    if (tid == 0)
        out[0] = (float)(sd[0] / ((double)NB * NPTS * NPTS));
}

// ---------------------------------------------------------------------------
extern "C" void kernel_launch(void* const* d_in, const int* in_sizes, int n_in,
                              void* d_out, int out_size) {
    const float* X = (const float*)d_in[0];
    const float* Y = (const float*)d_in[1];

    cudaFuncSetAttribute(dist_kernel,
                         cudaFuncAttributeMaxDynamicSharedMemorySize, SMEM_REQ);

    prep_kernel<<<4096, 256>>>(X, Y);
    dist_kernel<<<N_CTAS, 256, SMEM_REQ>>>();
    finalize_kernel<<<1, 256>>>((float*)d_out);
}